// round 1
// baseline (speedup 1.0000x reference)
#include <cuda_runtime.h>

#define B_   16
#define CH_  64
#define H_   128
#define W_   128
#define TOK  16384           // H_*W_
#define CNT  (16.0f*16384.0f) // B_*TOK (batchnorm count)

// ---------------- device scratch (static globals: allocation-free) -------------
__device__ float g_XT[B_*TOK*CH_];      // residual stream, BHWC
__device__ float g_V [B_*TOK*CH_];      // v projection / reused post-transformer
__device__ float g_P [B_*TOK*CH_];      // depthwise conv output
__device__ float g_C    [B_*64*64];     // per-batch gram of XT
__device__ float g_Weff [B_*64*64];     // attn folded into proj
__device__ float g_stats[256];          // [sum1|sumsq1|sum2|sumsq2] per channel
__device__ float g_pooled[B_*64*64];    // 8x8 pooled sums per (b,c)
__device__ float g_minmax[2];
__device__ float g_gate[B_*64];

__device__ __forceinline__ float leaky(float x){ return x >= 0.f ? x : 0.2f*x; }

// acc[64] += xc * wrow[0..63]  (wrow smem, 16B aligned)
__device__ __forceinline__ void mm_acc(float* acc, float xc, const float* wrow){
  const float4* w4 = (const float4*)wrow;
#pragma unroll
  for (int o4 = 0; o4 < 16; o4++){
    float4 w = w4[o4];
    acc[4*o4+0] = fmaf(xc, w.x, acc[4*o4+0]);
    acc[4*o4+1] = fmaf(xc, w.y, acc[4*o4+1]);
    acc[4*o4+2] = fmaf(xc, w.z, acc[4*o4+2]);
    acc[4*o4+3] = fmaf(xc, w.w, acc[4*o4+3]);
  }
}

// ---------------- kernel: NCHW -> BHWC transpose of input ----------------------
__global__ void k_transpose_in(const float* __restrict__ x){
  int b = blockIdx.x, n0 = blockIdx.y * 64;
  __shared__ float s[64*65];
  const float* xb = x + (size_t)b*CH_*TOK;
  for (int idx = threadIdx.x; idx < 4096; idx += 256){
    int c = idx >> 6, j = idx & 63;
    s[c*65 + j] = xb[(size_t)c*TOK + n0 + j];
  }
  __syncthreads();
  float* xt = g_XT + ((size_t)b*TOK + n0)*CH_;
  for (int idx = threadIdx.x; idx < 4096; idx += 256){
    int j = idx >> 6, c = idx & 63;
    xt[j*CH_ + c] = s[c*65 + j];
  }
}

// ---------------- kernel: V = XT @ wv, plus partial gram C = XT^T XT -----------
__global__ void k_v_gram(const float* __restrict__ wv){
  extern __shared__ float sm[];
  float* xs = sm;          // 256*65
  float* ws = sm + 16640;  // 4096
  int b = blockIdx.x, n0 = blockIdx.y * 256;
  const float* xt = g_XT + ((size_t)b*TOK + n0)*CH_;
  for (int idx = threadIdx.x; idx < 16384; idx += 256){
    int t = idx >> 6, c = idx & 63;
    xs[t*65 + c] = xt[idx];
  }
  for (int idx = threadIdx.x; idx < 4096; idx += 256) ws[idx] = wv[idx];
  __syncthreads();

  // V: one token per thread
  int t = threadIdx.x;
  float acc[64];
#pragma unroll
  for (int o = 0; o < 64; o++) acc[o] = 0.f;
  const float* row = &xs[t*65];
#pragma unroll 4
  for (int c = 0; c < 64; c++) mm_acc(acc, row[c], &ws[c*64]);
  float4* vout = (float4*)(g_V + ((size_t)b*TOK + n0 + t)*CH_);
#pragma unroll
  for (int o4 = 0; o4 < 16; o4++)
    vout[o4] = make_float4(acc[4*o4], acc[4*o4+1], acc[4*o4+2], acc[4*o4+3]);

  // partial gram: thread -> 4x4 tile of C (stride-16 layout)
  int a = threadIdx.x >> 4, bb = threadIdx.x & 15;
  float g[16];
#pragma unroll
  for (int i = 0; i < 16; i++) g[i] = 0.f;
  for (int tt = 0; tt < 256; tt++){
    const float* r = &xs[tt*65];
    float x1[4], x2[4];
#pragma unroll
    for (int k = 0; k < 4; k++){ x1[k] = r[a + 16*k]; x2[k] = r[bb + 16*k]; }
#pragma unroll
    for (int i = 0; i < 4; i++)
#pragma unroll
      for (int j = 0; j < 4; j++) g[i*4+j] = fmaf(x1[i], x2[j], g[i*4+j]);
  }
  float* Cb = g_C + b*4096;
#pragma unroll
  for (int i = 0; i < 4; i++)
#pragma unroll
    for (int j = 0; j < 4; j++)
      atomicAdd(&Cb[(a + 16*i)*64 + (bb + 16*j)], g[i*4+j]);
}

// ------- kernel: per-batch attention stats + fold into Weff (tiny, 16 blocks) ---
__global__ void k_attn_weff(const float* __restrict__ wq, const float* __restrict__ wk,
                            const float* __restrict__ wproj){
  extern __shared__ float sm[];
  float* Cs  = sm;            // 4096
  float* wqs = sm + 4096;
  float* wks = sm + 8192;
  float* wps = sm + 12288;
  float* T1  = sm + 16384;    // C @ wq
  float* T2  = sm + 20480;    // C @ wk
  __shared__ float attn_s[512];  // [h*8+dd][e]
  __shared__ float qq[64], kk[64];
  int b = blockIdx.x;
  for (int i = threadIdx.x; i < 4096; i += 256){
    Cs[i]  = g_C[b*4096 + i];
    wqs[i] = wq[i]; wks[i] = wk[i]; wps[i] = wproj[i];
  }
  __syncthreads();
  for (int i = threadIdx.x; i < 4096; i += 256){
    int r = i >> 6, e = i & 63; float s1 = 0.f, s2 = 0.f;
    for (int c = 0; c < 64; c++){
      float cv = Cs[r*64 + c];
      s1 = fmaf(cv, wqs[c*64 + e], s1);
      s2 = fmaf(cv, wks[c*64 + e], s2);
    }
    T1[i] = s1; T2[i] = s2;
  }
  __syncthreads();
  if (threadIdx.x < 64){
    int e = threadIdx.x; float s1 = 0.f, s2 = 0.f;
    for (int c = 0; c < 64; c++){
      s1 = fmaf(wqs[c*64 + e], T1[c*64 + e], s1);
      s2 = fmaf(wks[c*64 + e], T2[c*64 + e], s2);
    }
    qq[e] = s1; kk[e] = s2;
  }
  __syncthreads();
  if (threadIdx.x < 64){
    int h = threadIdx.x >> 3, dd = threadIdx.x & 7;
    float nk = fmaxf(sqrtf(kk[h*8 + dd]), 1e-12f);
    float lo[8]; float mx = -3.4e38f;
#pragma unroll
    for (int e = 0; e < 8; e++){
      float gg = 0.f;
      for (int c = 0; c < 64; c++)
        gg = fmaf(wks[c*64 + h*8 + dd], T1[c*64 + h*8 + e], gg);
      float nq = fmaxf(sqrtf(qq[h*8 + e]), 1e-12f);
      lo[e] = gg / (nk * nq);
      mx = fmaxf(mx, lo[e]);
    }
    float sum = 0.f;
#pragma unroll
    for (int e = 0; e < 8; e++){ lo[e] = expf(lo[e] - mx); sum += lo[e]; }
    float inv = 1.f / sum;
#pragma unroll
    for (int e = 0; e < 8; e++) attn_s[(h*8 + dd)*8 + e] = lo[e] * inv;
  }
  __syncthreads();
  // Weff[h*8+e][oc] = sum_dd attn[h,dd,e] * wproj[h*8+dd][oc]
  for (int i = threadIdx.x; i < 4096; i += 256){
    int cin = i >> 6, oc = i & 63;
    int h = cin >> 3, e = cin & 7;
    float s = 0.f;
#pragma unroll
    for (int dd = 0; dd < 8; dd++)
      s = fmaf(attn_s[(h*8 + dd)*8 + e], wps[(h*8 + dd)*64 + oc], s);
    g_Weff[b*4096 + i] = s;
  }
}

// ---------------- kernel: depthwise 3x3 on V -> P (BHWC) -----------------------
__global__ void k_dwconv(const float* __restrict__ wpos){
  int bh = blockIdx.x; int b = bh >> 7; int y = bh & 127;
  int cg = threadIdx.x & 15;
  int x  = blockIdx.y * 16 + (threadIdx.x >> 4);
  __shared__ float wp[576];
  for (int i = threadIdx.x; i < 576; i += 256) wp[i] = wpos[i];
  __syncthreads();
  float a0 = 0.f, a1 = 0.f, a2 = 0.f, a3 = 0.f;
  const float* Vb = g_V + (size_t)b*TOK*CH_;
#pragma unroll
  for (int ky = 0; ky < 3; ky++){
    int yy = y + ky - 1; if (yy < 0 || yy > 127) continue;
#pragma unroll
    for (int kx = 0; kx < 3; kx++){
      int xx = x + kx - 1; if (xx < 0 || xx > 127) continue;
      float4 v = *(const float4*)&Vb[((size_t)yy*128 + xx)*64 + cg*4];
      int wi = ky*3 + kx;
      a0 = fmaf(v.x, wp[(cg*4+0)*9 + wi], a0);
      a1 = fmaf(v.y, wp[(cg*4+1)*9 + wi], a1);
      a2 = fmaf(v.z, wp[(cg*4+2)*9 + wi], a2);
      a3 = fmaf(v.w, wp[(cg*4+3)*9 + wi], a3);
    }
  }
  *(float4*)&g_P[((size_t)b*TOK + y*128 + x)*64 + cg*4] = make_float4(a0,a1,a2,a3);
}

// ---------------- kernel: epilogue  XT += (V @ Weff_b + bproj) * P --------------
__global__ void k_epilogue(const float* __restrict__ bproj){
  extern __shared__ float sm[];
  float* xs = sm;           // 256*65
  float* ws = sm + 16640;   // 4096
  float* bp = ws + 4096;    // 64
  int b = blockIdx.x, n0 = blockIdx.y * 256;
  const float* V = g_V + ((size_t)b*TOK + n0)*CH_;
  for (int idx = threadIdx.x; idx < 16384; idx += 256){
    int t = idx >> 6, c = idx & 63;
    xs[t*65 + c] = V[idx];
  }
  for (int idx = threadIdx.x; idx < 4096; idx += 256) ws[idx] = g_Weff[b*4096 + idx];
  if (threadIdx.x < 64) bp[threadIdx.x] = bproj[threadIdx.x];
  __syncthreads();
  int t = threadIdx.x;
  float acc[64];
#pragma unroll
  for (int o = 0; o < 64; o++) acc[o] = bp[o];
  const float* row = &xs[t*65];
#pragma unroll 4
  for (int c = 0; c < 64; c++) mm_acc(acc, row[c], &ws[c*64]);
  __syncthreads();
  float* orow = &xs[t*65];
#pragma unroll
  for (int o = 0; o < 64; o++) orow[o] = acc[o];
  __syncthreads();
  float* XT = g_XT + ((size_t)b*TOK + n0)*CH_;
  const float* P = g_P + ((size_t)b*TOK + n0)*CH_;
  for (int idx = threadIdx.x; idx < 16384; idx += 256)
    XT[idx] += xs[(idx >> 6)*65 + (idx & 63)] * P[idx];
}

// ---------------- kernel: XT += LayerNorm(XT) @ wff ----------------------------
__global__ void k_lnff(const float* __restrict__ wff, const float* __restrict__ lng,
                       const float* __restrict__ lnb){
  extern __shared__ float sm[];
  float* xs = sm;
  float* ws = sm + 16640;
  float* gs = ws + 4096;
  float* bs = gs + 64;
  int b = blockIdx.x, n0 = blockIdx.y * 256;
  float* XT = g_XT + ((size_t)b*TOK + n0)*CH_;
  for (int idx = threadIdx.x; idx < 16384; idx += 256){
    int t = idx >> 6, c = idx & 63;
    xs[t*65 + c] = XT[idx];
  }
  for (int idx = threadIdx.x; idx < 4096; idx += 256) ws[idx] = wff[idx];
  if (threadIdx.x < 64){ gs[threadIdx.x] = lng[threadIdx.x]; bs[threadIdx.x] = lnb[threadIdx.x]; }
  __syncthreads();
  int t = threadIdx.x;
  const float* row = &xs[t*65];
  float m = 0.f, v = 0.f;
#pragma unroll 4
  for (int c = 0; c < 64; c++){ float xv = row[c]; m += xv; v = fmaf(xv, xv, v); }
  m *= (1.f/64.f);
  v = v*(1.f/64.f) - m*m;
  float rstd = rsqrtf(v + 1e-5f);
  float acc[64];
#pragma unroll
  for (int o = 0; o < 64; o++) acc[o] = 0.f;
#pragma unroll 4
  for (int c = 0; c < 64; c++){
    float yn = (row[c] - m) * rstd * gs[c] + bs[c];
    mm_acc(acc, yn, &ws[c*64]);
  }
  __syncthreads();
  float* orow = &xs[t*65];
#pragma unroll
  for (int o = 0; o < 64; o++) orow[o] = acc[o];
  __syncthreads();
  for (int idx = threadIdx.x; idx < 16384; idx += 256)
    XT[idx] += xs[(idx >> 6)*65 + (idx & 63)];
}

// ------------- kernel: per-channel stats of leaky(XT) (BN1) --------------------
__global__ void k_bnstats(){
  size_t base = (size_t)blockIdx.x * 16384;
  float s = 0.f, ss = 0.f;
  for (int k = 0; k < 64; k++){
    float x = g_XT[base + k*256 + threadIdx.x];
    x = leaky(x);
    s += x; ss = fmaf(x, x, ss);
  }
  __shared__ float red[512];
  red[threadIdx.x] = s; red[256 + threadIdx.x] = ss;
  __syncthreads();
  if (threadIdx.x < 64){
    float a  = red[threadIdx.x] + red[threadIdx.x+64] + red[threadIdx.x+128] + red[threadIdx.x+192];
    float a2 = red[256+threadIdx.x] + red[320+threadIdx.x] + red[384+threadIdx.x] + red[448+threadIdx.x];
    atomicAdd(&g_stats[threadIdx.x], a);
    atomicAdd(&g_stats[64 + threadIdx.x], a2);
  }
}

// ------ kernel: r3 = BN1(leaky(XT)) @ wd -> g_V, plus stats of leaky(r3) --------
__global__ void k_bn_conv(const float* __restrict__ wd, const float* __restrict__ g1,
                          const float* __restrict__ b1){
  extern __shared__ float sm[];
  float* xs = sm;
  float* ws = sm + 16640;
  float* scale = ws + 4096;
  float* shift = scale + 64;
  __shared__ float red[512];
  int b = blockIdx.x, n0 = blockIdx.y * 256;
  if (threadIdx.x < 64){
    int c = threadIdx.x;
    float m   = g_stats[c]      * (1.f/CNT);
    float var = g_stats[64 + c] * (1.f/CNT) - m*m;
    float sc  = g1[c] * rsqrtf(var + 1e-4f);
    scale[c] = sc; shift[c] = b1[c] - m*sc;
  }
  const float* XT = g_XT + ((size_t)b*TOK + n0)*CH_;
  for (int idx = threadIdx.x; idx < 16384; idx += 256){
    int t = idx >> 6, c = idx & 63;
    xs[t*65 + c] = XT[idx];
  }
  for (int idx = threadIdx.x; idx < 4096; idx += 256) ws[idx] = wd[idx];
  __syncthreads();
  int t = threadIdx.x;
  float acc[64];
#pragma unroll
  for (int o = 0; o < 64; o++) acc[o] = 0.f;
  const float* row = &xs[t*65];
#pragma unroll 4
  for (int c = 0; c < 64; c++){
    float xv = leaky(row[c]) * scale[c] + shift[c];
    mm_acc(acc, xv, &ws[c*64]);
  }
  __syncthreads();
  float* orow = &xs[t*65];
#pragma unroll
  for (int o = 0; o < 64; o++) orow[o] = acc[o];
  __syncthreads();
  float* Vo = g_V + ((size_t)b*TOK + n0)*CH_;
  float s = 0.f, ss = 0.f;
  for (int idx = threadIdx.x; idx < 16384; idx += 256){
    float f = xs[(idx >> 6)*65 + (idx & 63)];
    Vo[idx] = f;
    float lf = leaky(f);
    s += lf; ss = fmaf(lf, lf, ss);
  }
  red[threadIdx.x] = s; red[256 + threadIdx.x] = ss;
  __syncthreads();
  if (threadIdx.x < 64){
    float a  = red[threadIdx.x] + red[threadIdx.x+64] + red[threadIdx.x+128] + red[threadIdx.x+192];
    float a2 = red[256+threadIdx.x] + red[320+threadIdx.x] + red[384+threadIdx.x] + red[448+threadIdx.x];
    atomicAdd(&g_stats[128 + threadIdx.x], a);
    atomicAdd(&g_stats[192 + threadIdx.x], a2);
  }
}

// ---- kernel: s = BN2(leaky(r3)) + x_orig -> d_out (NCHW) + pooled sums ---------
__global__ void k_bn2_add_pool(const float* __restrict__ x_orig, float* __restrict__ out,
                               const float* __restrict__ g2, const float* __restrict__ b2){
  int b = blockIdx.x, n0 = blockIdx.y * 64;
  __shared__ float s[64*65];
  __shared__ float scale[64], shift[64];
  if (threadIdx.x < 64){
    int c = threadIdx.x;
    float m   = g_stats[128 + c] * (1.f/CNT);
    float var = g_stats[192 + c] * (1.f/CNT) - m*m;
    float sc  = g2[c] * rsqrtf(var + 1e-4f);
    scale[c] = sc; shift[c] = b2[c] - m*sc;
  }
  const float* R = g_V + ((size_t)b*TOK + n0)*CH_;
  for (int idx = threadIdx.x; idx < 4096; idx += 256){
    int t = idx >> 6, c = idx & 63;
    s[t*65 + c] = R[idx];
  }
  __syncthreads();
  int y = n0 >> 7, x0 = n0 & 127;
  int iblk = y >> 4, jbase = x0 >> 4;
  const float* xb = x_orig + (size_t)b*CH_*TOK;
  float* ob = out + (size_t)b*CH_*TOK;
  for (int idx = threadIdx.x; idx < 4096; idx += 256){
    int c = idx >> 6, j = idx & 63;
    float f = leaky(s[j*65 + c]) * scale[c] + shift[c];
    size_t off = (size_t)c*TOK + n0 + j;
    float sval = f + xb[off];
    ob[off] = sval;
    // reduce groups of 16 lanes (same c, same 16-wide pooling block)
    float r = sval;
    r += __shfl_down_sync(0xffffffffu, r, 8, 16);
    r += __shfl_down_sync(0xffffffffu, r, 4, 16);
    r += __shfl_down_sync(0xffffffffu, r, 2, 16);
    r += __shfl_down_sync(0xffffffffu, r, 1, 16);
    if ((threadIdx.x & 15) == 0){
      int jblk = jbase + (j >> 4);
      atomicAdd(&g_pooled[(b*64 + c)*64 + iblk*8 + jblk], r);
    }
  }
}

// ---------------- kernel: global min/max over pooled means ---------------------
__global__ void k_minmax(){
  float mn = 3.4e38f, mx = -3.4e38f;
  for (int i = threadIdx.x; i < B_*4096; i += 1024){
    float v = g_pooled[i] * (1.f/256.f);
    mn = fminf(mn, v); mx = fmaxf(mx, v);
  }
#pragma unroll
  for (int o = 16; o > 0; o >>= 1){
    mn = fminf(mn, __shfl_xor_sync(0xffffffffu, mn, o));
    mx = fmaxf(mx, __shfl_xor_sync(0xffffffffu, mx, o));
  }
  __shared__ float smn[32], smx[32];
  if ((threadIdx.x & 31) == 0){ smn[threadIdx.x >> 5] = mn; smx[threadIdx.x >> 5] = mx; }
  __syncthreads();
  if (threadIdx.x < 32){
    mn = smn[threadIdx.x]; mx = smx[threadIdx.x];
#pragma unroll
    for (int o = 16; o > 0; o >>= 1){
      mn = fminf(mn, __shfl_xor_sync(0xffffffffu, mn, o));
      mx = fmaxf(mx, __shfl_xor_sync(0xffffffffu, mx, o));
    }
    if (threadIdx.x == 0){ g_minmax[0] = mn; g_minmax[1] = mx; }
  }
}

// ---------------- kernel: SAA correlation + SE gate (per batch) ----------------
__global__ void k_gate(const float* __restrict__ w1, const float* __restrict__ w2){
  int b = blockIdx.x;
  __shared__ float y[4096];
  __shared__ float S[64];
  __shared__ float g0[64];
  __shared__ float hid[4];
  float mn = g_minmax[0];
  float inv = 1.f / (g_minmax[1] - mn);
  for (int i = threadIdx.x; i < 4096; i += 64)
    y[i] = (g_pooled[b*4096 + i] * (1.f/256.f) - mn) * inv;
  __syncthreads();
  {
    int i = threadIdx.x; float s = 0.f;
    for (int c = 0; c < 64; c++) s += y[c*64 + i];
    S[i] = s;
  }
  __syncthreads();
  {
    int c = threadIdx.x; float s = 0.f, sm2 = 0.f;
    for (int i = 0; i < 64; i++){
      s = fmaf(y[c*64 + i], S[i], s);
      sm2 += g_pooled[b*4096 + c*64 + i];
    }
    g0[c] = (s * (1.f/64.f)) * (sm2 * (1.f/16384.f));
  }
  __syncthreads();
  if (threadIdx.x < 4){
    int j = threadIdx.x; float h = 0.f;
    for (int c = 0; c < 64; c++) h = fmaf(g0[c], w1[c*4 + j], h);
    hid[j] = leaky(h);
  }
  __syncthreads();
  {
    int c = threadIdx.x; float o = 0.f;
#pragma unroll
    for (int j = 0; j < 4; j++) o = fmaf(hid[j], w2[j*64 + c], o);
    g_gate[b*64 + c] = 1.f / (1.f + expf(-o));
  }
}

// ---------------- kernel: d_out *= gate[b,c] (NCHW) ----------------------------
__global__ void k_scale(float* __restrict__ out){
  size_t i = (size_t)blockIdx.x * 256 + threadIdx.x;
  out[i] *= g_gate[i >> 14];
}

// ================================ launch ========================================
extern "C" void kernel_launch(void* const* d_in, const int* in_sizes, int n_in,
                              void* d_out, int out_size){
  const float* x     = (const float*)d_in[0];
  const float* wq    = (const float*)d_in[1];
  const float* wk    = (const float*)d_in[2];
  const float* wv    = (const float*)d_in[3];
  const float* wproj = (const float*)d_in[4];
  const float* bproj = (const float*)d_in[5];
  const float* wpos  = (const float*)d_in[6];
  const float* ln_g  = (const float*)d_in[7];
  const float* ln_b  = (const float*)d_in[8];
  const float* wff   = (const float*)d_in[9];
  const float* bn1_g = (const float*)d_in[10];
  const float* bn1_b = (const float*)d_in[11];
  const float* wd    = (const float*)d_in[12];
  const float* bn2_g = (const float*)d_in[13];
  const float* bn2_b = (const float*)d_in[14];
  const float* sw1   = (const float*)d_in[15];
  const float* sw2   = (const float*)d_in[16];
  float* out = (float*)d_out;

  cudaFuncSetAttribute(k_v_gram,    cudaFuncAttributeMaxDynamicSharedMemorySize, 96*1024);
  cudaFuncSetAttribute(k_attn_weff, cudaFuncAttributeMaxDynamicSharedMemorySize, 100*1024);
  cudaFuncSetAttribute(k_epilogue,  cudaFuncAttributeMaxDynamicSharedMemorySize, 96*1024);
  cudaFuncSetAttribute(k_lnff,      cudaFuncAttributeMaxDynamicSharedMemorySize, 96*1024);
  cudaFuncSetAttribute(k_bn_conv,   cudaFuncAttributeMaxDynamicSharedMemorySize, 96*1024);

  void *pC = nullptr, *pStats = nullptr, *pPooled = nullptr;
  cudaGetSymbolAddress(&pC, g_C);
  cudaGetSymbolAddress(&pStats, g_stats);
  cudaGetSymbolAddress(&pPooled, g_pooled);

  const size_t smA = (16640 + 4096) * sizeof(float);

  k_transpose_in<<<dim3(16, 256), 256>>>(x);
  for (int l = 0; l < 2; l++){
    cudaMemsetAsync(pC, 0, 16*4096*sizeof(float));
    k_v_gram<<<dim3(16, 64), 256, smA>>>(wv + l*4096);
    k_attn_weff<<<16, 256, 6*4096*sizeof(float)>>>(wq + l*4096, wk + l*4096, wproj + l*4096);
    k_dwconv<<<dim3(16*128, 8), 256>>>(wpos + l*576);
    k_epilogue<<<dim3(16, 64), 256, (16640 + 4096 + 64)*sizeof(float)>>>(bproj + l*64);
    k_lnff<<<dim3(16, 64), 256, (16640 + 4096 + 128)*sizeof(float)>>>(wff + l*4096, ln_g + l*64, ln_b + l*64);
  }
  cudaMemsetAsync(pStats, 0, 256*sizeof(float));
  k_bnstats<<<1024, 256>>>();
  k_bn_conv<<<dim3(16, 64), 256, (16640 + 4096 + 128)*sizeof(float)>>>(wd, bn1_g, bn1_b);
  cudaMemsetAsync(pPooled, 0, 16*4096*sizeof(float));
  k_bn2_add_pool<<<dim3(16, 256), 256>>>(x, out, bn2_g, bn2_b);
  k_minmax<<<1, 1024>>>();
  k_gate<<<16, 64>>>(sw1, sw2);
  k_scale<<<65536, 256>>>(out);
}